// round 1
// baseline (speedup 1.0000x reference)
#include <cuda_runtime.h>

typedef unsigned long long u64;

#define N_Q   65536
#define N_P   16384
#define C_OUT 512
#define C_IN  1024
#define SEGS  4
#define QPS   (N_Q/SEGS)   // 16384
#define PPS   (N_P/SEGS)   // 4096

// ---------------- device scratch (no allocations allowed) ----------------
__device__ float  g_x2[(size_t)N_P * C_OUT];   // 32 MB: relu(bn(feat_2 @ W2))
__device__ float4 g_p4[N_P];                   // packed points {x,y,z,|p|^2}
__device__ int    g_idx[N_Q * 3];
__device__ float  g_w[N_Q * 3];
__device__ float  g_s1[C_OUT], g_t1[C_OUT], g_s2[C_OUT], g_t2[C_OUT];

// ---------------- f32x2 packed-FMA helpers (sm_103a) ----------------
__device__ __forceinline__ u64 pack2(float x) {
    u64 r; asm("mov.b64 %0, {%1, %1};" : "=l"(r) : "f"(x)); return r;
}
__device__ __forceinline__ void ffma2(u64 &d, u64 a, u64 b) {
    asm("fma.rn.f32x2 %0, %1, %2, %0;" : "+l"(d) : "l"(a), "l"(b));
}
__device__ __forceinline__ void unpack2(u64 v, float &lo, float &hi) {
    asm("mov.b64 {%0, %1}, %2;" : "=f"(lo), "=f"(hi) : "l"(v));
}

// ---------------- prep: fold BN(+bias) into scale/shift; pack points ----------------
__global__ void prep_scales_kernel(const float* __restrict__ b1, const float* __restrict__ g1,
                                   const float* __restrict__ be1, const float* __restrict__ m1,
                                   const float* __restrict__ v1,
                                   const float* __restrict__ b2, const float* __restrict__ g2,
                                   const float* __restrict__ be2, const float* __restrict__ m2,
                                   const float* __restrict__ v2)
{
    int j = threadIdx.x;
    float s1 = g1[j] * rsqrtf(v1[j] + 1e-5f);
    g_s1[j] = s1;
    g_t1[j] = fmaf(b1[j] - m1[j], s1, be1[j]);
    float s2 = g2[j] * rsqrtf(v2[j] + 1e-5f);
    g_s2[j] = s2;
    g_t2[j] = fmaf(b2[j] - m2[j], s2, be2[j]);
}

__global__ void prep_points_kernel(const float* __restrict__ p2)
{
    int i = blockIdx.x * 256 + threadIdx.x;
    float x = p2[3*i], y = p2[3*i+1], z = p2[3*i+2];
    // match jnp.sum(p*p, -1): (x*x + y*y) + z*z, no FMA contraction
    float pp = __fadd_rn(__fadd_rn(__fmul_rn(x,x), __fmul_rn(y,y)), __fmul_rn(z,z));
    g_p4[i] = make_float4(x, y, z, pp);
}

// ---------------- fused GEMM + BN + ReLU (f32x2 packed FFMA) ----------------
// C[M, 512] = relu( (A[M,K] @ W[K,512]) * scale + shift )
#define BM 128
#define BN 128
#define BK 16

__global__ void __launch_bounds__(256, 2)
gemm_bn_relu_kernel(const float* __restrict__ A, const float* __restrict__ W,
                    float* __restrict__ Cext, int M, int K, int which)
{
    __shared__ u64   As2[BK][BM];   // A values pre-duplicated as {a,a} pairs (16 KB)
    __shared__ float Bs[BK][BN];    // 8 KB

    const float* scl = (which == 1) ? g_s1 : g_s2;
    const float* sft = (which == 1) ? g_t1 : g_t2;
    float* C = (which == 1) ? Cext : g_x2;

    const int tid = threadIdx.x;
    const int bm = blockIdx.y * BM;
    const int bn = blockIdx.x * BN;

    const int tr8 = (tid >> 4) * 8;   // row group within tile
    const int tc8 = (tid & 15) * 8;   // col group within tile

    const int aRow = tid >> 2;            // 0..63
    const int aCol = (tid & 3) * 4;       // 0,4,8,12
    const int bRow = tid >> 5;            // 0..7
    const int bCol = (tid & 31) * 4;      // 0..124

    u64 acc[8][4];
    #pragma unroll
    for (int i = 0; i < 8; i++)
        #pragma unroll
        for (int j = 0; j < 4; j++) acc[i][j] = 0ull;

    const float* Ab = A + (size_t)bm * K;
    const float* Wb = W + bn;

    for (int k0 = 0; k0 < K; k0 += BK) {
        #pragma unroll
        for (int r = 0; r < 2; r++) {
            int row = aRow + r * 64;
            float4 v = *(const float4*)(Ab + (size_t)row * K + (k0 + aCol));
            As2[aCol + 0][row] = pack2(v.x);
            As2[aCol + 1][row] = pack2(v.y);
            As2[aCol + 2][row] = pack2(v.z);
            As2[aCol + 3][row] = pack2(v.w);
        }
        #pragma unroll
        for (int r = 0; r < 2; r++) {
            int krow = bRow + r * 8;
            float4 v = *(const float4*)(Wb + (size_t)(k0 + krow) * C_OUT + bCol);
            *(float4*)&Bs[krow][bCol] = v;
        }
        __syncthreads();
        #pragma unroll
        for (int kk = 0; kk < BK; kk++) {
            u64 m2[8], n2[4];
            #pragma unroll
            for (int h = 0; h < 4; h++)
                *(ulonglong2*)&m2[2*h] = *(const ulonglong2*)&As2[kk][tr8 + 2*h];
            const u64* bp = (const u64*)&Bs[kk][tc8];
            *(ulonglong2*)&n2[0] = *(const ulonglong2*)&bp[0];
            *(ulonglong2*)&n2[2] = *(const ulonglong2*)&bp[2];
            #pragma unroll
            for (int i = 0; i < 8; i++)
                #pragma unroll
                for (int j = 0; j < 4; j++)
                    ffma2(acc[i][j], m2[i], n2[j]);
        }
        __syncthreads();
    }

    float sc[8], sh[8];
    #pragma unroll
    for (int j = 0; j < 8; j++) { sc[j] = scl[bn + tc8 + j]; sh[j] = sft[bn + tc8 + j]; }

    #pragma unroll
    for (int i = 0; i < 8; i++) {
        int row = bm + tr8 + i;
        float o[8];
        #pragma unroll
        for (int j = 0; j < 4; j++) {
            float lo, hi;
            unpack2(acc[i][j], lo, hi);
            o[2*j]   = fmaxf(fmaf(lo, sc[2*j],   sh[2*j]),   0.0f);
            o[2*j+1] = fmaxf(fmaf(hi, sc[2*j+1], sh[2*j+1]), 0.0f);
        }
        float* cp = C + (size_t)row * C_OUT + bn + tc8;
        *(float4*)cp       = make_float4(o[0], o[1], o[2], o[3]);
        *(float4*)(cp + 4) = make_float4(o[4], o[5], o[6], o[7]);
    }
}

// ---------------- brute-force 3-NN per segment ----------------
#define KNN_THREADS 128
#define CHUNK 2048

__global__ void __launch_bounds__(KNN_THREADS)
knn_kernel(const float* __restrict__ point1)
{
    __shared__ float4 pts[CHUNK];   // 32 KB
    int qid = blockIdx.x * KNN_THREADS + threadIdx.x;
    int seg = qid >> 14;            // / QPS

    float qx = point1[3*qid], qy = point1[3*qid+1], qz = point1[3*qid+2];
    // match jnp.sum(q*q, -1)
    float qq = __fadd_rn(__fadd_rn(__fmul_rn(qx,qx), __fmul_rn(qy,qy)), __fmul_rn(qz,qz));

    float e0 = 3.4e38f, e1 = 3.4e38f, e2 = 3.4e38f;
    int   i0 = 0, i1 = 0, i2 = 0;

    const float4* pb = g_p4 + seg * PPS;
    for (int ch = 0; ch < PPS; ch += CHUNK) {
        for (int j = threadIdx.x; j < CHUNK; j += KNN_THREADS)
            pts[j] = pb[ch + j];
        __syncthreads();
        #pragma unroll 4
        for (int j = 0; j < CHUNK; j++) {
            float4 p = pts[j];
            // d2 = (qq + pp) - 2*(q.p)  with clamp AFTER, mirroring the reference
            float m = __fmul_rn(qx, p.x);
            m = fmaf(qy, p.y, m);
            m = fmaf(qz, p.z, m);
            float t = __fadd_rn(qq, p.w);
            float d = fmaf(-2.0f, m, t);
            float e = fmaxf(d, 0.0f);
            if (e < e2) {
                int gj = ch + j;
                if (e < e1) {
                    e2 = e1; i2 = i1;
                    if (e < e0) { e1 = e0; i1 = i0; e0 = e; i0 = gj; }
                    else        { e1 = e;  i1 = gj; }
                } else { e2 = e; i2 = gj; }
            }
        }
        __syncthreads();
    }

    float r0 = 1.0f / (e0 + 1e-8f);
    float r1 = 1.0f / (e1 + 1e-8f);
    float r2 = 1.0f / (e2 + 1e-8f);
    float s = __fadd_rn(__fadd_rn(r0, r1), r2);
    int base = seg * PPS;
    g_idx[3*qid]   = base + i0;  g_w[3*qid]   = r0 / s;
    g_idx[3*qid+1] = base + i1;  g_w[3*qid+1] = r1 / s;
    g_idx[3*qid+2] = base + i2;  g_w[3*qid+2] = r2 / s;
}

// ---------------- gather-interp + residual add (out already holds x1) ----------------
__global__ void interp_add_kernel(float* __restrict__ out)
{
    int gid = blockIdx.x * 256 + threadIdx.x;
    int row = gid >> 7;         // 512 cols = 128 float4 per row
    int c4  = gid & 127;
    int i0 = g_idx[3*row], i1 = g_idx[3*row+1], i2 = g_idx[3*row+2];
    float w0 = g_w[3*row], w1 = g_w[3*row+1], w2 = g_w[3*row+2];
    const float4* x2 = (const float4*)g_x2;
    float4 a = x2[i0 * 128 + c4];
    float4 b = x2[i1 * 128 + c4];
    float4 c = x2[i2 * 128 + c4];
    float4* op = (float4*)out + ((size_t)row * 128 + c4);
    float4 o = *op;
    o.x += fmaf(w2, c.x, fmaf(w1, b.x, w0 * a.x));
    o.y += fmaf(w2, c.y, fmaf(w1, b.y, w0 * a.y));
    o.z += fmaf(w2, c.z, fmaf(w1, b.z, w0 * a.z));
    o.w += fmaf(w2, c.w, fmaf(w1, b.w, w0 * a.w));
    *op = o;
}

// ---------------- launch ----------------
extern "C" void kernel_launch(void* const* d_in, const int* in_sizes, int n_in,
                              void* d_out, int out_size)
{
    const float* point_1 = (const float*)d_in[0];
    const float* feat_1  = (const float*)d_in[1];
    const float* point_2 = (const float*)d_in[2];
    const float* feat_2  = (const float*)d_in[3];
    const float* W1  = (const float*)d_in[4];
    const float* b1  = (const float*)d_in[5];
    const float* g1  = (const float*)d_in[6];
    const float* be1 = (const float*)d_in[7];
    const float* m1  = (const float*)d_in[8];
    const float* v1  = (const float*)d_in[9];
    const float* W2  = (const float*)d_in[10];
    const float* b2  = (const float*)d_in[11];
    const float* g2  = (const float*)d_in[12];
    const float* be2 = (const float*)d_in[13];
    const float* m2  = (const float*)d_in[14];
    const float* v2  = (const float*)d_in[15];
    float* out = (float*)d_out;

    prep_scales_kernel<<<1, C_OUT>>>(b1, g1, be1, m1, v1, b2, g2, be2, m2, v2);
    prep_points_kernel<<<N_P / 256, 256>>>(point_2);

    // x2 = relu(bn(feat_2 @ W2)) -> g_x2
    gemm_bn_relu_kernel<<<dim3(C_OUT / BN, N_P / BM), 256>>>(feat_2, W2, nullptr, N_P, C_IN, 2);

    // 3-NN (independent of GEMMs, needs only points)
    knn_kernel<<<N_Q / KNN_THREADS, KNN_THREADS>>>(point_1);

    // x1 = relu(bn(feat_1 @ W1)) -> out
    gemm_bn_relu_kernel<<<dim3(C_OUT / BN, N_Q / BM), 256>>>(feat_1, W1, out, N_Q, C_OUT, 1);

    // out += interp(g_x2, knn)
    interp_add_kernel<<<(N_Q * (C_OUT / 4)) / 256, 256>>>(out);
}

// round 4
// speedup vs baseline: 1.7393x; 1.7393x over previous
#include <cuda_runtime.h>
#include <cstdint>

#define N_Q   65536
#define N_P   16384
#define C_OUT 512
#define C_IN  1024
#define SEGS  4
#define QPS   (N_Q/SEGS)   // 16384
#define PPS   (N_P/SEGS)   // 4096

// ---------------- device scratch (referenced ONLY from device code) ----------------
__device__ float  g_x2[(size_t)N_P * C_OUT];     // 32 MB: relu(bn(feat_2 @ W2))
__device__ float  g_wt1[(size_t)C_OUT * C_OUT];  // W1^T [512,512], tf32-rounded
__device__ float  g_wt2[(size_t)C_OUT * C_IN];   // W2^T [512,1024], tf32-rounded
__device__ float4 g_p4[N_P];                     // packed points {x,y,z,|p|^2}
__device__ int    g_idx[N_Q * 3];
__device__ float  g_w[N_Q * 3];
__device__ float  g_s1[C_OUT], g_t1[C_OUT], g_s2[C_OUT], g_t2[C_OUT];

// ---------------- PTX helpers (baseline sm_80+ features only) ----------------
__device__ __forceinline__ uint32_t smem_u32(const void* p) {
    uint32_t a;
    asm("{ .reg .u64 t; cvta.to.shared.u64 t, %1; cvt.u32.u64 %0, t; }" : "=r"(a) : "l"(p));
    return a;
}
__device__ __forceinline__ void cp16(uint32_t dst, const void* src) {
    asm volatile("cp.async.cg.shared.global [%0], [%1], 16;" :: "r"(dst), "l"(src) : "memory");
}
__device__ __forceinline__ void cp_commit() {
    asm volatile("cp.async.commit_group;" ::: "memory");
}
__device__ __forceinline__ void cp_wait2() {
    asm volatile("cp.async.wait_group 2;" ::: "memory");
}
__device__ __forceinline__ uint32_t f2tf32(float x) {
    uint32_t r; asm("cvt.rna.tf32.f32 %0, %1;" : "=r"(r) : "f"(x)); return r;
}
__device__ __forceinline__ void mma_tf32(float* d, const uint32_t* a, const uint32_t* b) {
    asm volatile(
        "mma.sync.aligned.m16n8k8.row.col.f32.tf32.tf32.f32 "
        "{%0,%1,%2,%3}, {%4,%5,%6,%7}, {%8,%9}, {%0,%1,%2,%3};"
        : "+f"(d[0]), "+f"(d[1]), "+f"(d[2]), "+f"(d[3])
        : "r"(a[0]), "r"(a[1]), "r"(a[2]), "r"(a[3]), "r"(b[0]), "r"(b[1]));
}

// ---------------- prep kernels ----------------
__global__ void prep_scales_kernel(const float* __restrict__ b1, const float* __restrict__ g1,
                                   const float* __restrict__ be1, const float* __restrict__ m1,
                                   const float* __restrict__ v1,
                                   const float* __restrict__ b2, const float* __restrict__ g2,
                                   const float* __restrict__ be2, const float* __restrict__ m2,
                                   const float* __restrict__ v2)
{
    int j = threadIdx.x;
    float s1 = g1[j] * rsqrtf(v1[j] + 1e-5f);
    g_s1[j] = s1;
    g_t1[j] = fmaf(b1[j] - m1[j], s1, be1[j]);
    float s2 = g2[j] * rsqrtf(v2[j] + 1e-5f);
    g_s2[j] = s2;
    g_t2[j] = fmaf(b2[j] - m2[j], s2, be2[j]);
}

__global__ void prep_points_kernel(const float* __restrict__ p2)
{
    int i = blockIdx.x * 256 + threadIdx.x;
    float x = p2[3*i], y = p2[3*i+1], z = p2[3*i+2];
    float pp = __fadd_rn(__fadd_rn(__fmul_rn(x,x), __fmul_rn(y,y)), __fmul_rn(z,z));
    g_p4[i] = make_float4(x, y, z, pp);
}

// W [K, 512] row-major -> g_wt{1,2} [512, K] row-major, tf32-rounded (device-symbol dst)
__global__ void transpose_kernel(const float* __restrict__ W, int K, int which)
{
    float* __restrict__ Wt = (which == 1) ? g_wt1 : g_wt2;
    __shared__ float t[32][33];
    int n0 = blockIdx.x * 32, k0 = blockIdx.y * 32;
    int x = threadIdx.x, y = threadIdx.y;   // 32 x 8
    #pragma unroll
    for (int i = 0; i < 32; i += 8)
        t[y + i][x] = W[(size_t)(k0 + y + i) * C_OUT + n0 + x];
    __syncthreads();
    #pragma unroll
    for (int i = 0; i < 32; i += 8)
        Wt[(size_t)(n0 + y + i) * K + k0 + x] = __uint_as_float(f2tf32(t[x][y + i]));
}

// ---------------- tf32 mma.sync GEMM + BN + ReLU ----------------
// C[M,512] = relu( (A[M,K] @ Wt^T) * scale + shift );
// A = raw fp32 activations (rna->tf32 applied in-register), Wt pre-rounded K-major.
#define BK   16
#define NST  4
#define LDP  20                      // padded row length in floats (conflict-free)
#define TILE_F (128 * LDP)           // 2560 floats per operand tile
#define STAGE_F (2 * TILE_F)         // A + B per stage
#define GEMM_SMEM (NST * STAGE_F * 4)  // 81920 bytes

__global__ void __launch_bounds__(256, 1)
gemm_mma_kernel(const float* __restrict__ A, float* __restrict__ Cext, int K, int which)
{
    extern __shared__ __align__(16) float S[];
    const uint32_t smb = smem_u32(S);

    const float* __restrict__ B   = (which == 1) ? g_wt1 : g_wt2;
    const float* __restrict__ scl = (which == 1) ? g_s1  : g_s2;
    const float* __restrict__ sft = (which == 1) ? g_t1  : g_t2;
    float* __restrict__ C = (which == 1) ? Cext : g_x2;

    const int tid  = threadIdx.x;
    const int warp = tid >> 5;
    const int lane = tid & 31;
    const int wM = warp >> 2;        // 0..1
    const int wN = warp & 3;         // 0..3
    const int lq = lane >> 2;        // 0..7  (groupID)
    const int kk = lane & 3;         // 0..3  (threadID_in_group)
    const int bm = blockIdx.y * 128;
    const int bn = blockIdx.x * 128;

    const int nchunk = K >> 4;       // K / 16

    float acc[4][4][4];
    #pragma unroll
    for (int mt = 0; mt < 4; mt++)
        #pragma unroll
        for (int nt = 0; nt < 4; nt++)
            #pragma unroll
            for (int r = 0; r < 4; r++) acc[mt][nt][r] = 0.0f;

    auto load_stage = [&](int s, int chunk) {
        const int k0 = chunk * BK;
        const uint32_t dA = smb + (uint32_t)s * (STAGE_F * 4);
        const uint32_t dB = dA + TILE_F * 4;
        #pragma unroll
        for (int i = 0; i < 2; i++) {
            int c = tid + i * 256;           // 0..511
            int row = c >> 2, seg = c & 3;
            uint32_t off = (uint32_t)row * (LDP * 4) + (uint32_t)seg * 16;
            cp16(dA + off, A + (size_t)(bm + row) * K + k0 + seg * 4);
            cp16(dB + off, B + (size_t)(bn + row) * K + k0 + seg * 4);
        }
    };

    // prologue: stages 0..NST-2
    #pragma unroll
    for (int c = 0; c < NST - 1; c++) { load_stage(c, c); cp_commit(); }

    for (int c = 0; c < nchunk; c++) {
        const int s = c & (NST - 1);
        cp_wait2();              // stage s data landed (<= NST-2 groups outstanding)
        __syncthreads();         // all warps done with slot being overwritten below

        if (c + NST - 1 < nchunk) load_stage((c + NST - 1) & (NST - 1), c + NST - 1);
        cp_commit();

        const float* As = S + s * STAGE_F;
        const float* Bs = As + TILE_F;

        #pragma unroll
        for (int ks = 0; ks < 2; ks++) {
            const int k8 = ks * 8 + kk;
            uint32_t a[4][4], b[4][2];
            #pragma unroll
            for (int mt = 0; mt < 4; mt++) {
                const float* ap = As + (wM * 64 + mt * 16 + lq) * LDP + k8;
                a[mt][0] = f2tf32(ap[0]);            // (row,   k)
                a[mt][1] = f2tf32(ap[8 * LDP]);      // (row+8, k)
                a[mt][2] = f2tf32(ap[4]);            // (row,   k+4)
                a[mt][3] = f2tf32(ap[8 * LDP + 4]);  // (row+8, k+4)
            }
            #pragma unroll
            for (int nt = 0; nt < 4; nt++) {
                const float* bp = Bs + (wN * 32 + nt * 8 + lq) * LDP + k8;
                b[nt][0] = __float_as_uint(bp[0]);   // already tf32-rounded
                b[nt][1] = __float_as_uint(bp[4]);
            }
            #pragma unroll
            for (int mt = 0; mt < 4; mt++)
                #pragma unroll
                for (int nt = 0; nt < 4; nt++)
                    mma_tf32(acc[mt][nt], a[mt], b[nt]);
        }
    }

    // epilogue: BN + ReLU, float2 stores
    const int colb = bn + wN * 32 + 2 * kk;
    float sc0[4], sc1[4], sh0[4], sh1[4];
    #pragma unroll
    for (int nt = 0; nt < 4; nt++) {
        int col = colb + nt * 8;
        sc0[nt] = __ldg(scl + col);     sc1[nt] = __ldg(scl + col + 1);
        sh0[nt] = __ldg(sft + col);     sh1[nt] = __ldg(sft + col + 1);
    }
    #pragma unroll
    for (int mt = 0; mt < 4; mt++) {
        const int r0 = bm + wM * 64 + mt * 16 + lq;
        #pragma unroll
        for (int nt = 0; nt < 4; nt++) {
            float2 v0, v1;
            v0.x = fmaxf(fmaf(acc[mt][nt][0], sc0[nt], sh0[nt]), 0.0f);
            v0.y = fmaxf(fmaf(acc[mt][nt][1], sc1[nt], sh1[nt]), 0.0f);
            v1.x = fmaxf(fmaf(acc[mt][nt][2], sc0[nt], sh0[nt]), 0.0f);
            v1.y = fmaxf(fmaf(acc[mt][nt][3], sc1[nt], sh1[nt]), 0.0f);
            *(float2*)(C + (size_t)r0 * C_OUT + colb + nt * 8)       = v0;
            *(float2*)(C + (size_t)(r0 + 8) * C_OUT + colb + nt * 8) = v1;
        }
    }
}

// ---------------- brute-force 3-NN per segment (round-1 passing, unchanged) ----------------
#define KNN_THREADS 128
#define CHUNK 2048

__global__ void __launch_bounds__(KNN_THREADS)
knn_kernel(const float* __restrict__ point1)
{
    __shared__ float4 pts[CHUNK];   // 32 KB
    int qid = blockIdx.x * KNN_THREADS + threadIdx.x;
    int seg = qid >> 14;

    float qx = point1[3*qid], qy = point1[3*qid+1], qz = point1[3*qid+2];
    float qq = __fadd_rn(__fadd_rn(__fmul_rn(qx,qx), __fmul_rn(qy,qy)), __fmul_rn(qz,qz));

    float e0 = 3.4e38f, e1 = 3.4e38f, e2 = 3.4e38f;
    int   i0 = 0, i1 = 0, i2 = 0;

    const float4* pb = g_p4 + seg * PPS;
    for (int ch = 0; ch < PPS; ch += CHUNK) {
        for (int j = threadIdx.x; j < CHUNK; j += KNN_THREADS)
            pts[j] = pb[ch + j];
        __syncthreads();
        #pragma unroll 4
        for (int j = 0; j < CHUNK; j++) {
            float4 p = pts[j];
            float m = __fmul_rn(qx, p.x);
            m = fmaf(qy, p.y, m);
            m = fmaf(qz, p.z, m);
            float t = __fadd_rn(qq, p.w);
            float d = fmaf(-2.0f, m, t);
            float e = fmaxf(d, 0.0f);
            if (e < e2) {
                int gj = ch + j;
                if (e < e1) {
                    e2 = e1; i2 = i1;
                    if (e < e0) { e1 = e0; i1 = i0; e0 = e; i0 = gj; }
                    else        { e1 = e;  i1 = gj; }
                } else { e2 = e; i2 = gj; }
            }
        }
        __syncthreads();
    }

    float r0 = 1.0f / (e0 + 1e-8f);
    float r1 = 1.0f / (e1 + 1e-8f);
    float r2 = 1.0f / (e2 + 1e-8f);
    float s = __fadd_rn(__fadd_rn(r0, r1), r2);
    int base = seg * PPS;
    g_idx[3*qid]   = base + i0;  g_w[3*qid]   = r0 / s;
    g_idx[3*qid+1] = base + i1;  g_w[3*qid+1] = r1 / s;
    g_idx[3*qid+2] = base + i2;  g_w[3*qid+2] = r2 / s;
}

// ---------------- gather-interp + residual add (out already holds x1) ----------------
__global__ void interp_add_kernel(float* __restrict__ out)
{
    int gid = blockIdx.x * 256 + threadIdx.x;
    int row = gid >> 7;
    int c4  = gid & 127;
    int i0 = g_idx[3*row], i1 = g_idx[3*row+1], i2 = g_idx[3*row+2];
    float w0 = g_w[3*row], w1 = g_w[3*row+1], w2 = g_w[3*row+2];
    const float4* x2 = (const float4*)g_x2;
    float4 a = x2[(size_t)i0 * 128 + c4];
    float4 b = x2[(size_t)i1 * 128 + c4];
    float4 c = x2[(size_t)i2 * 128 + c4];
    float4* op = (float4*)out + ((size_t)row * 128 + c4);
    float4 o = *op;
    o.x += fmaf(w2, c.x, fmaf(w1, b.x, w0 * a.x));
    o.y += fmaf(w2, c.y, fmaf(w1, b.y, w0 * a.y));
    o.z += fmaf(w2, c.z, fmaf(w1, b.z, w0 * a.z));
    o.w += fmaf(w2, c.w, fmaf(w1, b.w, w0 * a.w));
    *op = o;
}

// ---------------- launch ----------------
extern "C" void kernel_launch(void* const* d_in, const int* in_sizes, int n_in,
                              void* d_out, int out_size)
{
    const float* point_1 = (const float*)d_in[0];
    const float* feat_1  = (const float*)d_in[1];
    const float* point_2 = (const float*)d_in[2];
    const float* feat_2  = (const float*)d_in[3];
    const float* W1  = (const float*)d_in[4];
    const float* b1  = (const float*)d_in[5];
    const float* g1  = (const float*)d_in[6];
    const float* be1 = (const float*)d_in[7];
    const float* m1  = (const float*)d_in[8];
    const float* v1  = (const float*)d_in[9];
    const float* W2  = (const float*)d_in[10];
    const float* b2  = (const float*)d_in[11];
    const float* g2  = (const float*)d_in[12];
    const float* be2 = (const float*)d_in[13];
    const float* m2  = (const float*)d_in[14];
    const float* v2  = (const float*)d_in[15];
    float* out = (float*)d_out;

    cudaFuncSetAttribute(gemm_mma_kernel, cudaFuncAttributeMaxDynamicSharedMemorySize, GEMM_SMEM);

    prep_scales_kernel<<<1, C_OUT>>>(b1, g1, be1, m1, v1, b2, g2, be2, m2, v2);
    prep_points_kernel<<<N_P / 256, 256>>>(point_2);

    transpose_kernel<<<dim3(16, C_IN / 32), dim3(32, 8)>>>(W2, C_IN, 2);
    transpose_kernel<<<dim3(16, C_OUT / 32), dim3(32, 8)>>>(W1, C_OUT, 1);

    // x2 = relu(bn(feat_2 @ W2)) -> g_x2
    gemm_mma_kernel<<<dim3(C_OUT / 128, N_P / 128), 256, GEMM_SMEM>>>(feat_2, nullptr, C_IN, 2);

    // 3-NN (independent of GEMMs, needs only points)
    knn_kernel<<<N_Q / KNN_THREADS, KNN_THREADS>>>(point_1);

    // x1 = relu(bn(feat_1 @ W1)) -> out
    gemm_mma_kernel<<<dim3(C_OUT / 128, N_Q / 128), 256, GEMM_SMEM>>>(feat_1, out, C_OUT, 1);

    // out += interp(g_x2, knn)
    interp_add_kernel<<<(N_Q * (C_OUT / 4)) / 256, 256>>>(out);
}

// round 5
// speedup vs baseline: 2.8276x; 1.6257x over previous
#include <cuda_runtime.h>
#include <cstdint>

#define N_Q   65536
#define N_P   16384
#define C_OUT 512
#define C_IN  1024
#define SEGS  4
#define QPS   (N_Q/SEGS)   // 16384
#define PPS   (N_P/SEGS)   // 4096

// ---------------- device scratch (referenced ONLY from device code) ----------------
__device__ float  g_x2[(size_t)N_P * C_OUT];     // 32 MB: relu(bn(feat_2 @ W2))
__device__ float  g_wt1[(size_t)C_OUT * C_OUT];  // W1^T [512,512], tf32-rounded
__device__ float  g_wt2[(size_t)C_OUT * C_IN];   // W2^T [512,1024], tf32-rounded
__device__ float4 g_p4[N_P];                     // packed points {x,y,z,|p|^2}
__device__ int    g_idx[N_Q * 3];
__device__ float  g_w[N_Q * 3];
__device__ float  g_s1[C_OUT], g_t1[C_OUT], g_s2[C_OUT], g_t2[C_OUT];

// ---------------- PTX helpers (baseline sm_80+ features only) ----------------
__device__ __forceinline__ uint32_t smem_u32(const void* p) {
    uint32_t a;
    asm("{ .reg .u64 t; cvta.to.shared.u64 t, %1; cvt.u32.u64 %0, t; }" : "=r"(a) : "l"(p));
    return a;
}
__device__ __forceinline__ void cp16(uint32_t dst, const void* src) {
    asm volatile("cp.async.cg.shared.global [%0], [%1], 16;" :: "r"(dst), "l"(src) : "memory");
}
__device__ __forceinline__ void cp_commit() {
    asm volatile("cp.async.commit_group;" ::: "memory");
}
__device__ __forceinline__ void cp_wait2() {
    asm volatile("cp.async.wait_group 2;" ::: "memory");
}
__device__ __forceinline__ uint32_t f2tf32(float x) {
    uint32_t r; asm("cvt.rna.tf32.f32 %0, %1;" : "=r"(r) : "f"(x)); return r;
}
__device__ __forceinline__ void mma_tf32(float* d, const uint32_t* a, const uint32_t* b) {
    asm volatile(
        "mma.sync.aligned.m16n8k8.row.col.f32.tf32.tf32.f32 "
        "{%0,%1,%2,%3}, {%4,%5,%6,%7}, {%8,%9}, {%0,%1,%2,%3};"
        : "+f"(d[0]), "+f"(d[1]), "+f"(d[2]), "+f"(d[3])
        : "r"(a[0]), "r"(a[1]), "r"(a[2]), "r"(a[3]), "r"(b[0]), "r"(b[1]));
}

// ---------------- prep kernels ----------------
__global__ void prep_scales_kernel(const float* __restrict__ b1, const float* __restrict__ g1,
                                   const float* __restrict__ be1, const float* __restrict__ m1,
                                   const float* __restrict__ v1,
                                   const float* __restrict__ b2, const float* __restrict__ g2,
                                   const float* __restrict__ be2, const float* __restrict__ m2,
                                   const float* __restrict__ v2)
{
    int j = threadIdx.x;
    float s1 = g1[j] * rsqrtf(v1[j] + 1e-5f);
    g_s1[j] = s1;
    g_t1[j] = fmaf(b1[j] - m1[j], s1, be1[j]);
    float s2 = g2[j] * rsqrtf(v2[j] + 1e-5f);
    g_s2[j] = s2;
    g_t2[j] = fmaf(b2[j] - m2[j], s2, be2[j]);
}

__global__ void prep_points_kernel(const float* __restrict__ p2)
{
    int i = blockIdx.x * 256 + threadIdx.x;
    float x = p2[3*i], y = p2[3*i+1], z = p2[3*i+2];
    float pp = __fadd_rn(__fadd_rn(__fmul_rn(x,x), __fmul_rn(y,y)), __fmul_rn(z,z));
    g_p4[i] = make_float4(x, y, z, pp);
}

// W [K, 512] row-major -> g_wt{1,2} [512, K] row-major, tf32-rounded (device-symbol dst)
__global__ void transpose_kernel(const float* __restrict__ W, int K, int which)
{
    float* __restrict__ Wt = (which == 1) ? g_wt1 : g_wt2;
    __shared__ float t[32][33];
    int n0 = blockIdx.x * 32, k0 = blockIdx.y * 32;
    int x = threadIdx.x, y = threadIdx.y;   // 32 x 8
    #pragma unroll
    for (int i = 0; i < 32; i += 8)
        t[y + i][x] = W[(size_t)(k0 + y + i) * C_OUT + n0 + x];
    __syncthreads();
    #pragma unroll
    for (int i = 0; i < 32; i += 8)
        Wt[(size_t)(n0 + y + i) * K + k0 + x] = __uint_as_float(f2tf32(t[x][y + i]));
}

// ---------------- tf32 mma.sync GEMM + BN + ReLU ----------------
// C[M,512] = relu( (A[M,K] @ Wt^T) * scale + shift )
// CTA tile 256x128, 8 warps as 4(M) x 2(N), warp tile 64x64 (mt=4, nt=8).
#define BK   16
#define NST  4
#define LDP  20                          // padded row length (floats), conflict-free
#define A_TILE_F (256 * LDP)             // 5120 floats
#define B_TILE_F (128 * LDP)             // 2560 floats
#define STAGE_F  (A_TILE_F + B_TILE_F)   // 7680 floats = 30720 B
#define GEMM_SMEM (NST * STAGE_F * 4)    // 122880 B

__global__ void __launch_bounds__(256, 1)
gemm_mma_kernel(const float* __restrict__ A, float* __restrict__ Cext, int K, int which)
{
    extern __shared__ __align__(16) float S[];
    const uint32_t smb = smem_u32(S);

    const float* __restrict__ B   = (which == 1) ? g_wt1 : g_wt2;
    const float* __restrict__ scl = (which == 1) ? g_s1  : g_s2;
    const float* __restrict__ sft = (which == 1) ? g_t1  : g_t2;
    float* __restrict__ C = (which == 1) ? Cext : g_x2;

    const int tid  = threadIdx.x;
    const int warp = tid >> 5;
    const int lane = tid & 31;
    const int wM = warp >> 1;        // 0..3
    const int wN = warp & 1;         // 0..1
    const int lq = lane >> 2;        // 0..7  (groupID)
    const int kk = lane & 3;         // 0..3  (threadID_in_group)
    const int bm = blockIdx.y * 256;
    const int bn = blockIdx.x * 128;

    const int nchunk = K >> 4;       // K / 16

    float acc[4][8][4];
    #pragma unroll
    for (int mt = 0; mt < 4; mt++)
        #pragma unroll
        for (int nt = 0; nt < 8; nt++)
            #pragma unroll
            for (int r = 0; r < 4; r++) acc[mt][nt][r] = 0.0f;

    auto load_stage = [&](int s, int chunk) {
        const int k0 = chunk * BK;
        const uint32_t dA = smb + (uint32_t)s * (STAGE_F * 4);
        const uint32_t dB = dA + A_TILE_F * 4;
        #pragma unroll
        for (int i = 0; i < 4; i++) {            // A: 256x16 = 1024 float4
            int c = tid + i * 256;
            int row = c >> 2, seg = c & 3;
            cp16(dA + (uint32_t)row * (LDP * 4) + (uint32_t)seg * 16,
                 A + (size_t)(bm + row) * K + k0 + seg * 4);
        }
        #pragma unroll
        for (int i = 0; i < 2; i++) {            // B: 128x16 = 512 float4
            int c = tid + i * 256;
            int row = c >> 2, seg = c & 3;
            cp16(dB + (uint32_t)row * (LDP * 4) + (uint32_t)seg * 16,
                 B + (size_t)(bn + row) * K + k0 + seg * 4);
        }
    };

    // prologue: stages 0..NST-2
    #pragma unroll
    for (int c = 0; c < NST - 1; c++) { load_stage(c, c); cp_commit(); }

    for (int c = 0; c < nchunk; c++) {
        const int s = c & (NST - 1);
        cp_wait2();              // stage s data landed (<= NST-2 groups outstanding)
        __syncthreads();         // all warps done with slot being overwritten below

        if (c + NST - 1 < nchunk) load_stage((c + NST - 1) & (NST - 1), c + NST - 1);
        cp_commit();

        const float* As = S + s * STAGE_F;
        const float* Bs = As + A_TILE_F;

        #pragma unroll
        for (int ks = 0; ks < 2; ks++) {
            const int k8 = ks * 8 + kk;
            uint32_t a[4][4], b[8][2];
            #pragma unroll
            for (int mt = 0; mt < 4; mt++) {
                const float* ap = As + (wM * 64 + mt * 16 + lq) * LDP + k8;
                a[mt][0] = f2tf32(ap[0]);            // (row,   k)
                a[mt][1] = f2tf32(ap[8 * LDP]);      // (row+8, k)
                a[mt][2] = f2tf32(ap[4]);            // (row,   k+4)
                a[mt][3] = f2tf32(ap[8 * LDP + 4]);  // (row+8, k+4)
            }
            #pragma unroll
            for (int nt = 0; nt < 8; nt++) {
                const float* bp = Bs + (wN * 64 + nt * 8 + lq) * LDP + k8;
                b[nt][0] = __float_as_uint(bp[0]);   // already tf32-rounded
                b[nt][1] = __float_as_uint(bp[4]);
            }
            #pragma unroll
            for (int mt = 0; mt < 4; mt++)
                #pragma unroll
                for (int nt = 0; nt < 8; nt++)
                    mma_tf32(acc[mt][nt], a[mt], b[nt]);
        }
    }

    // epilogue: BN + ReLU, float2 stores
    const int colb = bn + wN * 64 + 2 * kk;
    float sc0[8], sc1[8], sh0[8], sh1[8];
    #pragma unroll
    for (int nt = 0; nt < 8; nt++) {
        int col = colb + nt * 8;
        sc0[nt] = __ldg(scl + col);     sc1[nt] = __ldg(scl + col + 1);
        sh0[nt] = __ldg(sft + col);     sh1[nt] = __ldg(sft + col + 1);
    }
    #pragma unroll
    for (int mt = 0; mt < 4; mt++) {
        const int r0 = bm + wM * 64 + mt * 16 + lq;
        #pragma unroll
        for (int nt = 0; nt < 8; nt++) {
            float2 v0, v1;
            v0.x = fmaxf(fmaf(acc[mt][nt][0], sc0[nt], sh0[nt]), 0.0f);
            v0.y = fmaxf(fmaf(acc[mt][nt][1], sc1[nt], sh1[nt]), 0.0f);
            v1.x = fmaxf(fmaf(acc[mt][nt][2], sc0[nt], sh0[nt]), 0.0f);
            v1.y = fmaxf(fmaf(acc[mt][nt][3], sc1[nt], sh1[nt]), 0.0f);
            *(float2*)(C + (size_t)r0 * C_OUT + colb + nt * 8)       = v0;
            *(float2*)(C + (size_t)(r0 + 8) * C_OUT + colb + nt * 8) = v1;
        }
    }
}

// ---------------- brute-force 3-NN, 2-way split scan per query ----------------
// Block: 256 threads = 128 queries x 2 halves. Half h scans points with (j&1)==h,
// keeping a strict-< top-3 (earliest index wins ties within the ascending scan).
// Merge: lexicographic (d2, idx) selection over the 6 candidates == global top_k order.
#define KNN_T 256
#define CHUNK 2048

__global__ void __launch_bounds__(KNN_T)
knn_kernel(const float* __restrict__ point1)
{
    __shared__ float4 pts[CHUNK];        // 32 KB
    __shared__ float  me[128][3];
    __shared__ int    mi[128][3];

    const int ql  = threadIdx.x & 127;
    const int h   = threadIdx.x >> 7;    // 0 or 1 (uniform per warp)
    const int qid = blockIdx.x * 128 + ql;
    const int seg = qid >> 14;

    float qx = point1[3*qid], qy = point1[3*qid+1], qz = point1[3*qid+2];
    float qq = __fadd_rn(__fadd_rn(__fmul_rn(qx,qx), __fmul_rn(qy,qy)), __fmul_rn(qz,qz));

    float e0 = 3.4e38f, e1 = 3.4e38f, e2 = 3.4e38f;
    int   i0 = 0, i1 = 0, i2 = 0;

    const float4* pb = g_p4 + seg * PPS;
    for (int ch = 0; ch < PPS; ch += CHUNK) {
        for (int j = threadIdx.x; j < CHUNK; j += KNN_T)
            pts[j] = pb[ch + j];
        __syncthreads();
        #pragma unroll 4
        for (int jj = 0; jj < CHUNK / 2; jj++) {
            int j = 2 * jj + h;
            float4 p = pts[j];
            float m = __fmul_rn(qx, p.x);
            m = fmaf(qy, p.y, m);
            m = fmaf(qz, p.z, m);
            float t = __fadd_rn(qq, p.w);
            float d = fmaf(-2.0f, m, t);
            float e = fmaxf(d, 0.0f);
            if (e < e2) {
                int gj = ch + j;
                if (e < e1) {
                    e2 = e1; i2 = i1;
                    if (e < e0) { e1 = e0; i1 = i0; e0 = e; i0 = gj; }
                    else        { e1 = e;  i1 = gj; }
                } else { e2 = e; i2 = gj; }
            }
        }
        __syncthreads();
    }

    if (h == 1) {
        me[ql][0] = e0; me[ql][1] = e1; me[ql][2] = e2;
        mi[ql][0] = i0; mi[ql][1] = i1; mi[ql][2] = i2;
    }
    __syncthreads();
    if (h == 0) {
        float ce[6] = { e0, e1, e2, me[ql][0], me[ql][1], me[ql][2] };
        int   ci[6] = { i0, i1, i2, mi[ql][0], mi[ql][1], mi[ql][2] };
        bool  used[6] = { false, false, false, false, false, false };
        float se[3]; int si[3];
        #pragma unroll
        for (int t = 0; t < 3; t++) {
            int best = -1; float be = 3.5e38f; int bi = 0x7FFFFFFF;
            #pragma unroll
            for (int s = 0; s < 6; s++) {
                if (used[s]) continue;
                if (ce[s] < be || (ce[s] == be && ci[s] < bi)) { be = ce[s]; bi = ci[s]; best = s; }
            }
            used[best] = true;
            se[t] = be; si[t] = bi;
        }
        float r0 = 1.0f / (se[0] + 1e-8f);
        float r1 = 1.0f / (se[1] + 1e-8f);
        float r2 = 1.0f / (se[2] + 1e-8f);
        float s = __fadd_rn(__fadd_rn(r0, r1), r2);
        int base = seg * PPS;
        g_idx[3*qid]   = base + si[0];  g_w[3*qid]   = r0 / s;
        g_idx[3*qid+1] = base + si[1];  g_w[3*qid+1] = r1 / s;
        g_idx[3*qid+2] = base + si[2];  g_w[3*qid+2] = r2 / s;
    }
}

// ---------------- gather-interp + residual add (out already holds x1) ----------------
__global__ void interp_add_kernel(float* __restrict__ out)
{
    int gid = blockIdx.x * 256 + threadIdx.x;
    int row = gid >> 7;
    int c4  = gid & 127;
    int i0 = g_idx[3*row], i1 = g_idx[3*row+1], i2 = g_idx[3*row+2];
    float w0 = g_w[3*row], w1 = g_w[3*row+1], w2 = g_w[3*row+2];
    const float4* x2 = (const float4*)g_x2;
    float4 a = x2[(size_t)i0 * 128 + c4];
    float4 b = x2[(size_t)i1 * 128 + c4];
    float4 c = x2[(size_t)i2 * 128 + c4];
    float4* op = (float4*)out + ((size_t)row * 128 + c4);
    float4 o = *op;
    o.x += fmaf(w2, c.x, fmaf(w1, b.x, w0 * a.x));
    o.y += fmaf(w2, c.y, fmaf(w1, b.y, w0 * a.y));
    o.z += fmaf(w2, c.z, fmaf(w1, b.z, w0 * a.z));
    o.w += fmaf(w2, c.w, fmaf(w1, b.w, w0 * a.w));
    *op = o;
}

// ---------------- launch ----------------
extern "C" void kernel_launch(void* const* d_in, const int* in_sizes, int n_in,
                              void* d_out, int out_size)
{
    const float* point_1 = (const float*)d_in[0];
    const float* feat_1  = (const float*)d_in[1];
    const float* point_2 = (const float*)d_in[2];
    const float* feat_2  = (const float*)d_in[3];
    const float* W1  = (const float*)d_in[4];
    const float* b1  = (const float*)d_in[5];
    const float* g1  = (const float*)d_in[6];
    const float* be1 = (const float*)d_in[7];
    const float* m1  = (const float*)d_in[8];
    const float* v1  = (const float*)d_in[9];
    const float* W2  = (const float*)d_in[10];
    const float* b2  = (const float*)d_in[11];
    const float* g2  = (const float*)d_in[12];
    const float* be2 = (const float*)d_in[13];
    const float* m2  = (const float*)d_in[14];
    const float* v2  = (const float*)d_in[15];
    float* out = (float*)d_out;

    cudaFuncSetAttribute(gemm_mma_kernel, cudaFuncAttributeMaxDynamicSharedMemorySize, GEMM_SMEM);

    prep_scales_kernel<<<1, C_OUT>>>(b1, g1, be1, m1, v1, b2, g2, be2, m2, v2);
    prep_points_kernel<<<N_P / 256, 256>>>(point_2);

    transpose_kernel<<<dim3(16, C_IN / 32), dim3(32, 8)>>>(W2, C_IN, 2);
    transpose_kernel<<<dim3(16, C_OUT / 32), dim3(32, 8)>>>(W1, C_OUT, 1);

    // x2 = relu(bn(feat_2 @ W2)) -> g_x2
    gemm_mma_kernel<<<dim3(C_OUT / 128, N_P / 256), 256, GEMM_SMEM>>>(feat_2, nullptr, C_IN, 2);

    // 3-NN (independent of GEMMs, needs only points)
    knn_kernel<<<N_Q / 128, KNN_T>>>(point_1);

    // x1 = relu(bn(feat_1 @ W1)) -> out
    gemm_mma_kernel<<<dim3(C_OUT / 128, N_Q / 256), 256, GEMM_SMEM>>>(feat_1, out, C_OUT, 1);

    // out += interp(g_x2, knn)
    interp_add_kernel<<<(N_Q * (C_OUT / 4)) / 256, 256>>>(out);
}